// round 6
// baseline (speedup 1.0000x reference)
#include <cuda_runtime.h>
#include <cuda_fp16.h>
#include <math.h>
#include <stdint.h>

#define B_ 4
#define N_ 4096
#define IN_DIM 256
#define OUT_DIM 128
#define NROWS (B_ * N_)
#define TJ 64              // j-tile (K of the aggregation MMA)
#define NT (N_ / TJ)       // 64 tiles
#define PADH 72            // smem half pitch for MMA tiles (144B rows)
#define RCTA 64            // rows per kAB CTA

// Scratch (no cudaMalloc allowed)
__device__ float  g_h [NROWS * OUT_DIM];          // fp32 h (k2 input)
__device__ __half g_hT[(size_t)B_ * OUT_DIM * N_];// f16 h transposed: [b][d][j]
__device__ float2 g_S [NROWS];                    // (exp(s/2), exp(s/10))
__device__ float2 g_E [NROWS];                    // (exp(d/2), exp(d/10))

// ---------------------------------------------------------------------------
__device__ __forceinline__ uint32_t sm_u32(const void* p) {
    uint32_t a;
    asm("{ .reg .u64 t; cvta.to.shared.u64 t, %1; cvt.u32.u64 %0, t; }"
        : "=r"(a) : "l"(p));
    return a;
}
__device__ __forceinline__ void cp16(uint32_t dst, const void* src) {
    asm volatile("cp.async.cg.shared.global [%0], [%1], 16;"
                 :: "r"(dst), "l"(src));
}
__device__ __forceinline__ void cp_commit() {
    asm volatile("cp.async.commit_group;" ::: "memory");
}
template <int N>
__device__ __forceinline__ void cp_wait() {
    asm volatile("cp.async.wait_group %0;" :: "n"(N) : "memory");
}
__device__ __forceinline__ void ldsm_x4(uint32_t& r0, uint32_t& r1,
                                        uint32_t& r2, uint32_t& r3,
                                        uint32_t addr) {
    asm volatile("ldmatrix.sync.aligned.m8n8.x4.shared.b16 {%0,%1,%2,%3}, [%4];"
                 : "=r"(r0), "=r"(r1), "=r"(r2), "=r"(r3) : "r"(addr));
}
__device__ __forceinline__ void mma16816(float* c,
                                         uint32_t a0, uint32_t a1,
                                         uint32_t a2, uint32_t a3,
                                         uint32_t b0, uint32_t b1) {
    asm volatile("mma.sync.aligned.m16n8k16.row.col.f32.f16.f16.f32 "
                 "{%0,%1,%2,%3},{%4,%5,%6,%7},{%8,%9},{%0,%1,%2,%3};"
                 : "+f"(c[0]), "+f"(c[1]), "+f"(c[2]), "+f"(c[3])
                 : "r"(a0), "r"(a1), "r"(a2), "r"(a3), "r"(b0), "r"(b1));
}

// ---------------------------------------------------------------------------
// k1: h = x @ W  (64-row blocks, grid 256)
// ---------------------------------------------------------------------------
__global__ void __launch_bounds__(256) k1_gemm(const float* __restrict__ x,
                                               const float* __restrict__ W) {
    __shared__ float xs[32][68];
    __shared__ float ws[32][128];
    const int tid = threadIdx.x;
    const int m0  = blockIdx.x * 64;
    const int tm  = (tid >> 4) << 2;
    const int tn  = (tid & 15) << 2;

    float acc[4][8];
#pragma unroll
    for (int i = 0; i < 4; i++)
#pragma unroll
        for (int j = 0; j < 8; j++) acc[i][j] = 0.f;

    for (int k0 = 0; k0 < IN_DIM; k0 += 32) {
#pragma unroll
        for (int i = 0; i < 2; i++) {
            int f   = tid + 256 * i;
            int row = f >> 3;
            int kc  = (f & 7) << 2;
            float4 v = *(const float4*)&x[(size_t)(m0 + row) * IN_DIM + k0 + kc];
            xs[kc + 0][row] = v.x;
            xs[kc + 1][row] = v.y;
            xs[kc + 2][row] = v.z;
            xs[kc + 3][row] = v.w;
        }
#pragma unroll
        for (int i = 0; i < 4; i++) {
            int f   = tid + 256 * i;
            int row = f >> 5;
            int c   = (f & 31) << 2;
            *(float4*)&ws[row][c] = *(const float4*)&W[(size_t)(k0 + row) * OUT_DIM + c];
        }
        __syncthreads();
#pragma unroll
        for (int kk = 0; kk < 32; kk++) {
            float4 a  = *(float4*)&xs[kk][tm];
            float4 b0 = *(float4*)&ws[kk][tn];
            float4 b1 = *(float4*)&ws[kk][tn + 64];
            float av[4] = {a.x, a.y, a.z, a.w};
            float bv[8] = {b0.x, b0.y, b0.z, b0.w, b1.x, b1.y, b1.z, b1.w};
#pragma unroll
            for (int i = 0; i < 4; i++)
#pragma unroll
                for (int j = 0; j < 8; j++) acc[i][j] += av[i] * bv[j];
        }
        __syncthreads();
    }
#pragma unroll
    for (int i = 0; i < 4; i++) {
        size_t ro = (size_t)(m0 + tm + i) * OUT_DIM;
        *(float4*)&g_h[ro + tn]      = make_float4(acc[i][0], acc[i][1], acc[i][2], acc[i][3]);
        *(float4*)&g_h[ro + tn + 64] = make_float4(acc[i][4], acc[i][5], acc[i][6], acc[i][7]);
    }
    const int b    = m0 >> 12;
    const int mloc = (m0 & (N_ - 1)) + tm;
#pragma unroll
    for (int j = 0; j < 8; j++) {
        int col = (j < 4) ? (tn + j) : (tn + 60 + j);
        __half2 q0 = __floats2half2_rn(acc[0][j], acc[1][j]);
        __half2 q1 = __floats2half2_rn(acc[2][j], acc[3][j]);
        uint2 u;
        u.x = *(uint32_t*)&q0; u.y = *(uint32_t*)&q1;
        *(uint2*)&g_hT[((size_t)(b * OUT_DIM + col)) * N_ + mloc] = u;
    }
}

// ---------------------------------------------------------------------------
// k2: exp factor tables. exp(leaky(t)/2) = max(exp(t/2), exp(t/10))
// ---------------------------------------------------------------------------
__global__ void __launch_bounds__(256) k2_sd(const float* __restrict__ a_src,
                                             const float* __restrict__ a_dst) {
    const int warp = threadIdx.x >> 5, lane = threadIdx.x & 31;
    const int row  = blockIdx.x * 8 + warp;
    float4 hv = *(const float4*)&g_h[(size_t)row * OUT_DIM + lane * 4];
    float4 as = *(const float4*)&a_src[lane * 4];
    float4 ad = *(const float4*)&a_dst[lane * 4];
    float s = hv.x * as.x + hv.y * as.y + hv.z * as.z + hv.w * as.w;
    float d = hv.x * ad.x + hv.y * ad.y + hv.z * ad.z + hv.w * ad.w;
#pragma unroll
    for (int o = 16; o; o >>= 1) {
        s += __shfl_xor_sync(0xffffffffu, s, o);
        d += __shfl_xor_sync(0xffffffffu, d, o);
    }
    if (lane == 0) {
        g_S[row] = make_float2(expf(s * 0.5f), expf(s * 0.1f));
        g_E[row] = make_float2(expf(d * 0.5f), expf(d * 0.1f));
    }
}

// ---------------------------------------------------------------------------
// kAB: fused masked-softmax weights + mma.sync f16 aggregation.
// 3-stage cp.async pipeline: raw A fp32 + hT f16 land in SMEM with no
// register staging; weight pass reads SMEM, writes f16 alpha; MMA consumes.
// Grid 256 CTAs (64 rows), 2 CTAs/SM.
// ---------------------------------------------------------------------------
#define ARAW_B   (RCTA * TJ * 4)            // 16384
#define HT_B     (OUT_DIM * PADH * 2)       // 18432
#define ALPHA_B  (RCTA * PADH * 2)          // 9216
#define HT_OFF   (3 * ARAW_B)               // 49152
#define AL_OFF   (HT_OFF + 3 * HT_B)        // 104448
#define DSM_BYTES (AL_OFF + ALPHA_B)        // 113664

__global__ void __launch_bounds__(256, 2) kAB(const float* __restrict__ A,
                                              float* __restrict__ out) {
    extern __shared__ __align__(16) char dsm[];
    __shared__ float s_z[RCTA];

    const int tid  = threadIdx.x;
    const int wid  = tid >> 5, lane = tid & 31;
    const int batch = blockIdx.x >> 6;
    const int row0  = (blockIdx.x & 63) << 6;
    const size_t rbase = (size_t)batch * N_;

    const uint32_t smb = sm_u32(dsm);
    const float*  Ab  = A + (rbase + row0) * (size_t)N_;
    const __half* hTb = g_hT + (size_t)batch * OUT_DIM * N_;

    // cp.async chunk mapping (4 A-chunks + 4 H-chunks per thread)
    const int a_row = tid >> 4, a_ch = (tid & 15);              // + i*16 rows
    const int h_dim = tid >> 3, h_ch = (tid & 7);               // + i*32 dims

    // weight-pass rows: wid*8..wid*8+7; lane handles cols 2l, 2l+1
    float S1[8], S2[8], z[8];
#pragma unroll
    for (int r = 0; r < 8; r++) {
        float2 sv = g_S[rbase + row0 + wid * 8 + r];
        S1[r] = sv.x; S2[r] = sv.y; z[r] = 0.f;
    }

    // MMA assignment
    const int mtile = wid & 3, nh = wid >> 2;
    const uint32_t aaddr_l = smb + AL_OFF
        + (uint32_t)((mtile * 16 + (lane & 15)) * (PADH * 2) + ((lane >> 4) << 4));
    const uint32_t baddr_l = (uint32_t)((nh * 64 + ((lane >> 4) << 3) + (lane & 7)) * (PADH * 2)
        + (((lane >> 3) & 1) << 4));

    float c[8][4];
#pragma unroll
    for (int q = 0; q < 8; q++)
        c[q][0] = c[q][1] = c[q][2] = c[q][3] = 0.f;

#define ISSUE_TILE(T, S)                                                      \
    do {                                                                      \
        const int jt_ = (T) * TJ;                                             \
        uint32_t ad_ = smb + (S) * ARAW_B;                                    \
        uint32_t hd_ = smb + HT_OFF + (S) * HT_B;                             \
        _Pragma("unroll")                                                     \
        for (int i = 0; i < 4; i++) {                                         \
            int rr = a_row + i * 16;                                          \
            cp16(ad_ + rr * 256 + a_ch * 16,                                  \
                 Ab + (size_t)rr * N_ + jt_ + a_ch * 4);                      \
        }                                                                     \
        _Pragma("unroll")                                                     \
        for (int i = 0; i < 4; i++) {                                         \
            int dd = h_dim + i * 32;                                          \
            cp16(hd_ + dd * (PADH * 2) + h_ch * 16,                           \
                 hTb + (size_t)dd * N_ + jt_ + h_ch * 8);                     \
        }                                                                     \
        cp_commit();                                                          \
    } while (0)

    ISSUE_TILE(0, 0);
    ISSUE_TILE(1, 1);

    for (int t = 0; t < NT; t++) {
        const int stage = t % 3;
        if (t + 1 < NT) cp_wait<1>();
        else            cp_wait<0>();
        __syncthreads();   // stage data visible; prev MMA done (alpha WAR safe)

        // weight pass: SMEM A -> f16 alpha
        {
            float4 Ev = ((const float4*)(g_E + rbase + t * TJ))[lane];
            const char* araw = dsm + stage * ARAW_B;
            __half* sal = (__half*)(dsm + AL_OFF);
#pragma unroll
            for (int r = 0; r < 8; r++) {
                int wr = wid * 8 + r;
                float2 av = *(const float2*)(araw + wr * 256 + lane * 8);
                float w0 = fmaxf(S1[r] * Ev.x, S2[r] * Ev.y);
                float w1 = fmaxf(S1[r] * Ev.z, S2[r] * Ev.w);
                w0 = av.x >= 1e-9f ? w0 : 0.f;
                w1 = av.y >= 1e-9f ? w1 : 0.f;
                z[r] += w0 + w1;
                *(__half2*)&sal[wr * PADH + 2 * lane] = __floats2half2_rn(w0, w1);
            }
        }
        if (t + 2 < NT) ISSUE_TILE(t + 2, (t + 2) % 3);
        __syncthreads();   // alpha ready

        // MMA: K=64 (4 k-steps), this warp: 16 m-rows x 64 n-dims
        const uint32_t bb = smb + HT_OFF + stage * HT_B + baddr_l;
#pragma unroll
        for (int ks = 0; ks < 4; ks++) {
            uint32_t a0, a1, a2, a3;
            ldsm_x4(a0, a1, a2, a3, aaddr_l + ks * 32);
#pragma unroll
            for (int p = 0; p < 4; p++) {
                uint32_t b0, b1, b2, b3;
                ldsm_x4(b0, b1, b2, b3, bb + p * (16 * PADH * 2) + ks * 32);
                mma16816(c[2 * p],     a0, a1, a2, a3, b0, b1);
                mma16816(c[2 * p + 1], a0, a1, a2, a3, b2, b3);
            }
        }
    }

    // z row sums
#pragma unroll
    for (int r = 0; r < 8; r++) {
        float zz = z[r];
#pragma unroll
        for (int o = 16; o; o >>= 1) zz += __shfl_xor_sync(0xffffffffu, zz, o);
        if (lane == 0) s_z[wid * 8 + r] = zz;
    }
    __syncthreads();

    // epilogue
    const int mlo = mtile * 16 + (lane >> 2);
    const float zlo = s_z[mlo], zhi = s_z[mlo + 8];
    const float invlo = zlo > 0.f ? 1.f / zlo : 0.f;
    const float invhi = zhi > 0.f ? 1.f / zhi : 0.f;
    float* olo = out + (rbase + row0 + mlo) * OUT_DIM + nh * 64 + 2 * (lane & 3);
    float* ohi = olo + 8 * OUT_DIM;
#pragma unroll
    for (int q = 0; q < 8; q++) {
        *(float2*)(olo + q * 8) = make_float2(c[q][0] * invlo, c[q][1] * invlo);
        *(float2*)(ohi + q * 8) = make_float2(c[q][2] * invhi, c[q][3] * invhi);
    }
}

// ---------------------------------------------------------------------------
extern "C" void kernel_launch(void* const* d_in, const int* in_sizes, int n_in,
                              void* d_out, int out_size) {
    const float* x     = (const float*)d_in[0];   // [4,4096,256]
    const float* A     = (const float*)d_in[1];   // [4,4096,4096]
    const float* W     = (const float*)d_in[2];   // [256,128]
    const float* a_src = (const float*)d_in[3];   // [128]
    const float* a_dst = (const float*)d_in[4];   // [128]
    float* out = (float*)d_out;                   // [4,4096,128]

    cudaFuncSetAttribute(kAB, cudaFuncAttributeMaxDynamicSharedMemorySize,
                         DSM_BYTES);

    k1_gemm<<<NROWS / 64, 256>>>(x, W);
    k2_sd  <<<NROWS / 8,  256>>>(a_src, a_dst);
    kAB    <<<NROWS / RCTA, 256, DSM_BYTES>>>(A, out);
    (void)in_sizes; (void)n_in; (void)out_size;
}

// round 7
// speedup vs baseline: 1.1973x; 1.1973x over previous
#include <cuda_runtime.h>
#include <cuda_fp16.h>
#include <math.h>
#include <stdint.h>

#define B_ 4
#define N_ 4096
#define IN_DIM 256
#define OUT_DIM 128
#define NROWS (B_ * N_)
#define TJ 64              // j-tile (K of the aggregation MMA)
#define NT (N_ / TJ)       // 64 tiles
#define PADH 72            // smem half pitch for MMA tiles (144B rows)
#define RCTA 64            // rows per kAB CTA

// Scratch (no cudaMalloc allowed)
__device__ float  g_h [NROWS * OUT_DIM];          // fp32 h (k2 input)
__device__ __half g_hT[(size_t)B_ * OUT_DIM * N_];// f16 h transposed: [b][d][j]
__device__ float2 g_S [NROWS];                    // (exp(s/2), exp(s/10))
__device__ float2 g_E [NROWS];                    // (exp(d/2), exp(d/10))

// ---------------------------------------------------------------------------
__device__ __forceinline__ uint32_t sm_u32(const void* p) {
    uint32_t a;
    asm("{ .reg .u64 t; cvta.to.shared.u64 t, %1; cvt.u32.u64 %0, t; }"
        : "=r"(a) : "l"(p));
    return a;
}
__device__ __forceinline__ void cp16(uint32_t dst, const void* src) {
    asm volatile("cp.async.cg.shared.global [%0], [%1], 16;"
                 :: "r"(dst), "l"(src));
}
__device__ __forceinline__ void cp_commit() {
    asm volatile("cp.async.commit_group;" ::: "memory");
}
template <int N>
__device__ __forceinline__ void cp_wait() {
    asm volatile("cp.async.wait_group %0;" :: "n"(N) : "memory");
}
__device__ __forceinline__ void ldsm_x4(uint32_t& r0, uint32_t& r1,
                                        uint32_t& r2, uint32_t& r3,
                                        uint32_t addr) {
    asm volatile("ldmatrix.sync.aligned.m8n8.x4.shared.b16 {%0,%1,%2,%3}, [%4];"
                 : "=r"(r0), "=r"(r1), "=r"(r2), "=r"(r3) : "r"(addr));
}
__device__ __forceinline__ void mma16816(float* c,
                                         uint32_t a0, uint32_t a1,
                                         uint32_t a2, uint32_t a3,
                                         uint32_t b0, uint32_t b1) {
    asm volatile("mma.sync.aligned.m16n8k16.row.col.f32.f16.f16.f32 "
                 "{%0,%1,%2,%3},{%4,%5,%6,%7},{%8,%9},{%0,%1,%2,%3};"
                 : "+f"(c[0]), "+f"(c[1]), "+f"(c[2]), "+f"(c[3])
                 : "r"(a0), "r"(a1), "r"(a2), "r"(a3), "r"(b0), "r"(b1));
}

// ---------------------------------------------------------------------------
// k1: h = x @ W  (64-row blocks, grid 256)
// ---------------------------------------------------------------------------
__global__ void __launch_bounds__(256) k1_gemm(const float* __restrict__ x,
                                               const float* __restrict__ W) {
    __shared__ float xs[32][68];
    __shared__ float ws[32][128];
    const int tid = threadIdx.x;
    const int m0  = blockIdx.x * 64;
    const int tm  = (tid >> 4) << 2;
    const int tn  = (tid & 15) << 2;

    float acc[4][8];
#pragma unroll
    for (int i = 0; i < 4; i++)
#pragma unroll
        for (int j = 0; j < 8; j++) acc[i][j] = 0.f;

    for (int k0 = 0; k0 < IN_DIM; k0 += 32) {
#pragma unroll
        for (int i = 0; i < 2; i++) {
            int f   = tid + 256 * i;
            int row = f >> 3;
            int kc  = (f & 7) << 2;
            float4 v = *(const float4*)&x[(size_t)(m0 + row) * IN_DIM + k0 + kc];
            xs[kc + 0][row] = v.x;
            xs[kc + 1][row] = v.y;
            xs[kc + 2][row] = v.z;
            xs[kc + 3][row] = v.w;
        }
#pragma unroll
        for (int i = 0; i < 4; i++) {
            int f   = tid + 256 * i;
            int row = f >> 5;
            int c   = (f & 31) << 2;
            *(float4*)&ws[row][c] = *(const float4*)&W[(size_t)(k0 + row) * OUT_DIM + c];
        }
        __syncthreads();
#pragma unroll
        for (int kk = 0; kk < 32; kk++) {
            float4 a  = *(float4*)&xs[kk][tm];
            float4 b0 = *(float4*)&ws[kk][tn];
            float4 b1 = *(float4*)&ws[kk][tn + 64];
            float av[4] = {a.x, a.y, a.z, a.w};
            float bv[8] = {b0.x, b0.y, b0.z, b0.w, b1.x, b1.y, b1.z, b1.w};
#pragma unroll
            for (int i = 0; i < 4; i++)
#pragma unroll
                for (int j = 0; j < 8; j++) acc[i][j] += av[i] * bv[j];
        }
        __syncthreads();
    }
#pragma unroll
    for (int i = 0; i < 4; i++) {
        size_t ro = (size_t)(m0 + tm + i) * OUT_DIM;
        *(float4*)&g_h[ro + tn]      = make_float4(acc[i][0], acc[i][1], acc[i][2], acc[i][3]);
        *(float4*)&g_h[ro + tn + 64] = make_float4(acc[i][4], acc[i][5], acc[i][6], acc[i][7]);
    }
    const int b    = m0 >> 12;
    const int mloc = (m0 & (N_ - 1)) + tm;
#pragma unroll
    for (int j = 0; j < 8; j++) {
        int col = (j < 4) ? (tn + j) : (tn + 60 + j);
        __half2 q0 = __floats2half2_rn(acc[0][j], acc[1][j]);
        __half2 q1 = __floats2half2_rn(acc[2][j], acc[3][j]);
        uint2 u;
        u.x = *(uint32_t*)&q0; u.y = *(uint32_t*)&q1;
        *(uint2*)&g_hT[((size_t)(b * OUT_DIM + col)) * N_ + mloc] = u;
    }
}

// ---------------------------------------------------------------------------
// k2: exp factor tables. exp(leaky(t)/2) = max(exp(t/2), exp(t/10))
// ---------------------------------------------------------------------------
__global__ void __launch_bounds__(256) k2_sd(const float* __restrict__ a_src,
                                             const float* __restrict__ a_dst) {
    const int warp = threadIdx.x >> 5, lane = threadIdx.x & 31;
    const int row  = blockIdx.x * 8 + warp;
    float4 hv = *(const float4*)&g_h[(size_t)row * OUT_DIM + lane * 4];
    float4 as = *(const float4*)&a_src[lane * 4];
    float4 ad = *(const float4*)&a_dst[lane * 4];
    float s = hv.x * as.x + hv.y * as.y + hv.z * as.z + hv.w * as.w;
    float d = hv.x * ad.x + hv.y * ad.y + hv.z * ad.z + hv.w * ad.w;
#pragma unroll
    for (int o = 16; o; o >>= 1) {
        s += __shfl_xor_sync(0xffffffffu, s, o);
        d += __shfl_xor_sync(0xffffffffu, d, o);
    }
    if (lane == 0) {
        g_S[row] = make_float2(expf(s * 0.5f), expf(s * 0.1f));
        g_E[row] = make_float2(expf(d * 0.5f), expf(d * 0.1f));
    }
}

// ---------------------------------------------------------------------------
// kAB: fused masked-softmax weights + mma.sync f16 aggregation.
// h: 3-stage cp.async. A: register prefetch (1-tile distance, full-tile gap).
// alpha: triple-buffered smem, weight pass runs one tile ahead of MMA ->
// ONE __syncthreads per tile. Warp split 2 (m) x 4 (n).
// ---------------------------------------------------------------------------
#define HT_B     (OUT_DIM * PADH * 2)       // 18432
#define ALPHA_B  (RCTA * PADH * 2)          // 9216
#define AL_OFF   (3 * HT_B)                 // 55296
#define DSM_BYTES (AL_OFF + 3 * ALPHA_B)    // 82944

__global__ void __launch_bounds__(256, 2) kAB(const float* __restrict__ A,
                                              float* __restrict__ out) {
    extern __shared__ __align__(16) char dsm[];
    __shared__ float s_z[RCTA];

    const int tid  = threadIdx.x;
    const int wid  = tid >> 5, lane = tid & 31;
    const int batch = blockIdx.x >> 6;
    const int row0  = (blockIdx.x & 63) << 6;
    const size_t rbase = (size_t)batch * N_;

    const uint32_t smb = sm_u32(dsm);
    const __half* hTb = g_hT + (size_t)batch * OUT_DIM * N_;

    // h cp.async mapping (4 chunks/thread)
    const int h_dim = tid >> 3, h_ch = tid & 7;

    // weight-pass rows: wid*8..+7; lane covers cols 2l, 2l+1
    float S1[8], S2[8], z[8];
#pragma unroll
    for (int r = 0; r < 8; r++) {
        float2 sv = g_S[rbase + row0 + wid * 8 + r];
        S1[r] = sv.x; S2[r] = sv.y; z[r] = 0.f;
    }
    const float* Abase = A + (rbase + row0 + wid * 8) * (size_t)N_ + 2 * lane;

    // MMA split: mh = wid&1 (32 rows), nq = wid>>1 (32 h-dims)
    const int mh = wid & 1, nq = wid >> 1;
    const uint32_t aoff_l = (uint32_t)((mh * 32 + (lane & 15)) * (PADH * 2)
                                       + ((lane >> 4) << 4));
    const uint32_t boff_l = (uint32_t)((nq * 32 + ((lane >> 4) << 3) + (lane & 7)) * (PADH * 2)
                                       + (((lane >> 3) & 1) << 4));

    float c[8][4];   // [mt*4+p][frag]
#pragma unroll
    for (int q = 0; q < 8; q++)
        c[q][0] = c[q][1] = c[q][2] = c[q][3] = 0.f;

    float2 Ar[8];
    float4 Ev;

#define ISSUE_H(T, S)                                                         \
    do {                                                                      \
        const int jt_ = (T) * TJ;                                             \
        uint32_t hd_ = smb + (S) * HT_B;                                      \
        _Pragma("unroll")                                                     \
        for (int i = 0; i < 4; i++) {                                         \
            int dd = h_dim + i * 32;                                          \
            cp16(hd_ + dd * (PADH * 2) + h_ch * 16,                           \
                 hTb + (size_t)dd * N_ + jt_ + h_ch * 8);                     \
        }                                                                     \
        cp_commit();                                                          \
    } while (0)

#define LOAD_A(T)                                                             \
    do {                                                                      \
        Ev = ((const float4*)(g_E + rbase + (T) * TJ))[lane];                 \
        _Pragma("unroll")                                                     \
        for (int r = 0; r < 8; r++)                                           \
            Ar[r] = *(const float2*)(Abase + (size_t)r * N_ + (T) * TJ);      \
    } while (0)

#define WEIGHT(T)                                                             \
    do {                                                                      \
        __half* sal = (__half*)(dsm + AL_OFF + ((T) % 3) * ALPHA_B);          \
        _Pragma("unroll")                                                     \
        for (int r = 0; r < 8; r++) {                                         \
            float w0 = fmaxf(S1[r] * Ev.x, S2[r] * Ev.y);                     \
            float w1 = fmaxf(S1[r] * Ev.z, S2[r] * Ev.w);                     \
            w0 = Ar[r].x >= 1e-9f ? w0 : 0.f;                                 \
            w1 = Ar[r].y >= 1e-9f ? w1 : 0.f;                                 \
            z[r] += w0 + w1;                                                  \
            *(__half2*)&sal[(wid * 8 + r) * PADH + 2 * lane] =                \
                __floats2half2_rn(w0, w1);                                    \
        }                                                                     \
    } while (0)

    // prologue: h(0), h(1) in flight; alpha(0) computed; A(1) loaded
    ISSUE_H(0, 0);
    ISSUE_H(1, 1);
    LOAD_A(0);
    WEIGHT(0);
    LOAD_A(1);

    for (int t = 0; t < NT; t++) {
        if (t + 2 < NT) cp_wait<1>();
        else            cp_wait<0>();
        __syncthreads();   // h(t) staged; alpha(t) visible; WAR distances safe

        if (t + 2 < NT) ISSUE_H(t + 2, (t + 2) % 3);
        if (t + 1 < NT) {
            WEIGHT(t + 1);                 // write alpha buf (t+1)%3
            if (t + 2 < NT) LOAD_A(t + 2); // regs free again; full-tile gap
        }

        // MMA on tile t: alpha buf t%3, h stage t%3
        const uint32_t ab = smb + AL_OFF + (t % 3) * ALPHA_B + aoff_l;
        const uint32_t hb = smb + (t % 3) * HT_B + boff_l;
#pragma unroll
        for (int ks = 0; ks < 4; ks++) {
            uint32_t a0, a1, a2, a3, a4, a5, a6, a7;
            ldsm_x4(a0, a1, a2, a3, ab + ks * 32);                    // mt0
            ldsm_x4(a4, a5, a6, a7, ab + 16 * (PADH * 2) + ks * 32);  // mt1
            uint32_t b0, b1, b2, b3, b4, b5, b6, b7;
            ldsm_x4(b0, b1, b2, b3, hb + ks * 32);                    // n8 p0,p1
            ldsm_x4(b4, b5, b6, b7, hb + 16 * (PADH * 2) + ks * 32);  // n8 p2,p3
            mma16816(c[0], a0, a1, a2, a3, b0, b1);
            mma16816(c[1], a0, a1, a2, a3, b2, b3);
            mma16816(c[2], a0, a1, a2, a3, b4, b5);
            mma16816(c[3], a0, a1, a2, a3, b6, b7);
            mma16816(c[4], a4, a5, a6, a7, b0, b1);
            mma16816(c[5], a4, a5, a6, a7, b2, b3);
            mma16816(c[6], a4, a5, a6, a7, b4, b5);
            mma16816(c[7], a4, a5, a6, a7, b6, b7);
        }
    }

    // z row sums
#pragma unroll
    for (int r = 0; r < 8; r++) {
        float zz = z[r];
#pragma unroll
        for (int o = 16; o; o >>= 1) zz += __shfl_xor_sync(0xffffffffu, zz, o);
        if (lane == 0) s_z[wid * 8 + r] = zz;
    }
    __syncthreads();

    // epilogue: c[mt*4+p] -> rows mh*32+mt*16+(l>>2)(+8), cols nq*32+p*8+2(l&3)
#pragma unroll
    for (int mt = 0; mt < 2; mt++) {
        const int rlo = mh * 32 + mt * 16 + (lane >> 2);
        const float zlo = s_z[rlo], zhi = s_z[rlo + 8];
        const float invlo = zlo > 0.f ? 1.f / zlo : 0.f;
        const float invhi = zhi > 0.f ? 1.f / zhi : 0.f;
        float* olo = out + (rbase + row0 + rlo) * OUT_DIM + nq * 32 + 2 * (lane & 3);
        float* ohi = olo + 8 * OUT_DIM;
#pragma unroll
        for (int p = 0; p < 4; p++) {
            const float* cf = c[mt * 4 + p];
            *(float2*)(olo + p * 8) = make_float2(cf[0] * invlo, cf[1] * invlo);
            *(float2*)(ohi + p * 8) = make_float2(cf[2] * invhi, cf[3] * invhi);
        }
    }
}

// ---------------------------------------------------------------------------
extern "C" void kernel_launch(void* const* d_in, const int* in_sizes, int n_in,
                              void* d_out, int out_size) {
    const float* x     = (const float*)d_in[0];   // [4,4096,256]
    const float* A     = (const float*)d_in[1];   // [4,4096,4096]
    const float* W     = (const float*)d_in[2];   // [256,128]
    const float* a_src = (const float*)d_in[3];   // [128]
    const float* a_dst = (const float*)d_in[4];   // [128]
    float* out = (float*)d_out;                   // [4,4096,128]

    cudaFuncSetAttribute(kAB, cudaFuncAttributeMaxDynamicSharedMemorySize,
                         DSM_BYTES);

    k1_gemm<<<NROWS / 64, 256>>>(x, W);
    k2_sd  <<<NROWS / 8,  256>>>(a_src, a_dst);
    kAB    <<<NROWS / RCTA, 256, DSM_BYTES>>>(A, out);
    (void)in_sizes; (void)n_in; (void)out_size;
}

// round 8
// speedup vs baseline: 1.4766x; 1.2333x over previous
#include <cuda_runtime.h>
#include <cuda_fp16.h>
#include <math.h>
#include <stdint.h>

#define B_ 4
#define N_ 4096
#define IN_DIM 256
#define OUT_DIM 128
#define NROWS (B_ * N_)
#define TJ 64              // j-tile (K of the aggregation MMA)
#define NT (N_ / TJ)       // 64 tiles
#define PADH 72            // smem half pitch for 64-k MMA tiles (144B rows)
#define RCTA 128           // rows per kAB CTA

// Scratch (no cudaMalloc allowed)
__device__ __half g_WT[OUT_DIM * IN_DIM];         // W^T f16: [d][k]
__device__ __half g_hT[(size_t)B_ * OUT_DIM * N_];// f16 h^T: [b][d][j]
__device__ float2 g_S [NROWS];                    // (exp(s/2), exp(s/10))
__device__ float2 g_E [NROWS];                    // (exp(d/2), exp(d/10))

// ---------------------------------------------------------------------------
__device__ __forceinline__ uint32_t sm_u32(const void* p) {
    uint32_t a;
    asm("{ .reg .u64 t; cvta.to.shared.u64 t, %1; cvt.u32.u64 %0, t; }"
        : "=r"(a) : "l"(p));
    return a;
}
__device__ __forceinline__ void cp16(uint32_t dst, const void* src) {
    asm volatile("cp.async.cg.shared.global [%0], [%1], 16;"
                 :: "r"(dst), "l"(src));
}
__device__ __forceinline__ void cp_commit() {
    asm volatile("cp.async.commit_group;" ::: "memory");
}
template <int N>
__device__ __forceinline__ void cp_wait() {
    asm volatile("cp.async.wait_group %0;" :: "n"(N) : "memory");
}
__device__ __forceinline__ void ldsm_x4(uint32_t& r0, uint32_t& r1,
                                        uint32_t& r2, uint32_t& r3,
                                        uint32_t addr) {
    asm volatile("ldmatrix.sync.aligned.m8n8.x4.shared.b16 {%0,%1,%2,%3}, [%4];"
                 : "=r"(r0), "=r"(r1), "=r"(r2), "=r"(r3) : "r"(addr));
}
__device__ __forceinline__ void mma16816(float* c,
                                         uint32_t a0, uint32_t a1,
                                         uint32_t a2, uint32_t a3,
                                         uint32_t b0, uint32_t b1) {
    asm volatile("mma.sync.aligned.m16n8k16.row.col.f32.f16.f16.f32 "
                 "{%0,%1,%2,%3},{%4,%5,%6,%7},{%8,%9},{%0,%1,%2,%3};"
                 : "+f"(c[0]), "+f"(c[1]), "+f"(c[2]), "+f"(c[3])
                 : "r"(a0), "r"(a1), "r"(a2), "r"(a3), "r"(b0), "r"(b1));
}

// ---------------------------------------------------------------------------
// kW: W[k][n] fp32 -> g_WT[n][k] f16 (8 CTAs, 32 k-rows each)
// ---------------------------------------------------------------------------
__global__ void __launch_bounds__(256) kW(const float* __restrict__ W) {
    __shared__ float sx[32][130];
    const int tid = threadIdx.x;
    const int kc0 = blockIdx.x * 32;
#pragma unroll
    for (int i = 0; i < 4; i++) {
        int f  = tid + 256 * i;          // 0..1023 float4 (32k x 32 chunks)
        int kk = f >> 5;
        int d4 = (f & 31) << 2;
        float4 v = *(const float4*)&W[(size_t)(kc0 + kk) * OUT_DIM + d4];
        sx[kk][d4 + 0] = v.x; sx[kk][d4 + 1] = v.y;
        sx[kk][d4 + 2] = v.z; sx[kk][d4 + 3] = v.w;
    }
    __syncthreads();
#pragma unroll
    for (int i = 0; i < 2; i++) {
        int f  = tid + 256 * i;          // 0..511: 128 d x 4 k8-chunks
        int d  = f >> 2;
        int k8 = (f & 3) << 3;
        __half2 h[4];
#pragma unroll
        for (int q = 0; q < 4; q++)
            h[q] = __floats2half2_rn(sx[k8 + 2 * q][d], sx[k8 + 2 * q + 1][d]);
        uint4 u;
        u.x = *(uint32_t*)&h[0]; u.y = *(uint32_t*)&h[1];
        u.z = *(uint32_t*)&h[2]; u.w = *(uint32_t*)&h[3];
        *(uint4*)&g_WT[(size_t)d * IN_DIM + kc0 + k8] = u;
    }
}

// ---------------------------------------------------------------------------
// k1: hT = W^T x^T via mma.sync f16 (M=d=128, N=j=128/CTA, K=256).
// Fused: s = h.a_src, d = h.a_dst from fp32 accums -> exp tables (kills k2).
// Output c-frags are hT layout -> direct STG.
// ---------------------------------------------------------------------------
#define WT_PITCH_B 528                      // 264 halves per d-row
#define WT_BYTES   (OUT_DIM * WT_PITCH_B)   // 67584
#define XS_BYTES   (128 * PADH * 2)         // 18432
#define K1_DSM     (WT_BYTES + 2 * XS_BYTES)// 104448

__global__ void __launch_bounds__(256) k1_gemm(const float* __restrict__ x,
                                               const float* __restrict__ a_src,
                                               const float* __restrict__ a_dst) {
    extern __shared__ __align__(16) char dsm[];
    __shared__ float s_sm[128], d_sm[128];

    const int tid  = threadIdx.x;
    const int wid  = tid >> 5, lane = tid & 31;
    const int j0g  = blockIdx.x * 128;        // global row of first j
    const int batch = j0g >> 12;
    const int jloc  = j0g & (N_ - 1);

    if (tid < 128) { s_sm[tid] = 0.f; d_sm[tid] = 0.f; }

    const uint32_t smb = sm_u32(dsm);

    // stage W^T f16 [128 d][256 k] into smem (pitch 528B), via cp.async
#pragma unroll
    for (int i = 0; i < 16; i++) {
        int f  = tid + 256 * i;               // 0..4095 16B chunks
        int d  = f >> 5, ch = f & 31;
        cp16(smb + d * WT_PITCH_B + ch * 16, g_WT + (size_t)d * IN_DIM + ch * 8);
    }
    cp_commit();

    // MMA split: mh = wid&1 (64 d), nq = wid>>1 (32 j)
    const int mh = wid & 1, nq = wid >> 1;
    const uint32_t aoff = (uint32_t)((mh * 64 + (lane & 15)) * WT_PITCH_B
                                     + ((lane >> 4) << 4));
    const uint32_t boff = (uint32_t)((nq * 32 + ((lane >> 4) << 3) + (lane & 7)) * (PADH * 2)
                                     + (((lane >> 3) & 1) << 4));

    // a_src/a_dst values for this thread's d rows
    float as0[4], as1[4], ad0[4], ad1[4];
#pragma unroll
    for (int mt = 0; mt < 4; mt++) {
        int d0 = mh * 64 + mt * 16 + (lane >> 2);
        as0[mt] = a_src[d0]; as1[mt] = a_src[d0 + 8];
        ad0[mt] = a_dst[d0]; ad1[mt] = a_dst[d0 + 8];
    }

    float c[16][4];
#pragma unroll
    for (int q = 0; q < 16; q++)
        c[q][0] = c[q][1] = c[q][2] = c[q][3] = 0.f;

    float4 XR[8];
    const int xj = tid >> 4, xk = (tid & 15) << 2;   // +i*16 rows

#define LDG_X(CH)                                                             \
    do {                                                                      \
        _Pragma("unroll")                                                     \
        for (int i = 0; i < 8; i++)                                           \
            XR[i] = *(const float4*)&x[(size_t)(j0g + xj + i * 16) * IN_DIM   \
                                       + (CH) * 64 + xk];                     \
    } while (0)

    LDG_X(0);
    cp_wait<0>();
    __syncthreads();

    for (int ch = 0; ch < 4; ch++) {
        // STS x chunk (f16) into buf ch&1
        {
            char* xb = dsm + WT_BYTES + (ch & 1) * XS_BYTES;
#pragma unroll
            for (int i = 0; i < 8; i++) {
                __half2 p0 = __floats2half2_rn(XR[i].x, XR[i].y);
                __half2 p1 = __floats2half2_rn(XR[i].z, XR[i].w);
                uint2 u; u.x = *(uint32_t*)&p0; u.y = *(uint32_t*)&p1;
                *(uint2*)(xb + (xj + i * 16) * (PADH * 2) + xk * 2) = u;
            }
        }
        __syncthreads();
        if (ch < 3) LDG_X(ch + 1);

        const uint32_t ab = smb + aoff + ch * 128;   // 64 k * 2B
        const uint32_t bb = smb + WT_BYTES + (ch & 1) * XS_BYTES + boff;
#pragma unroll
        for (int ks = 0; ks < 4; ks++) {
            uint32_t b0, b1, b2, b3, b4, b5, b6, b7;
            ldsm_x4(b0, b1, b2, b3, bb + ks * 32);
            ldsm_x4(b4, b5, b6, b7, bb + 16 * (PADH * 2) + ks * 32);
#pragma unroll
            for (int mt = 0; mt < 4; mt++) {
                uint32_t a0, a1, a2, a3;
                ldsm_x4(a0, a1, a2, a3, ab + mt * 16 * WT_PITCH_B + ks * 32);
                mma16816(c[mt * 4 + 0], a0, a1, a2, a3, b0, b1);
                mma16816(c[mt * 4 + 1], a0, a1, a2, a3, b2, b3);
                mma16816(c[mt * 4 + 2], a0, a1, a2, a3, b4, b5);
                mma16816(c[mt * 4 + 3], a0, a1, a2, a3, b6, b7);
            }
        }
        __syncthreads();
    }

    // s/d partial reductions over this warp's 64 d rows
#pragma unroll
    for (int nt = 0; nt < 4; nt++) {
#pragma unroll
        for (int q = 0; q < 2; q++) {
            float ps = 0.f, pd = 0.f;
#pragma unroll
            for (int mt = 0; mt < 4; mt++) {
                const float* cf = c[mt * 4 + nt];
                ps += cf[q] * as0[mt] + cf[q + 2] * as1[mt];
                pd += cf[q] * ad0[mt] + cf[q + 2] * ad1[mt];
            }
#pragma unroll
            for (int o = 4; o < 32; o <<= 1) {
                ps += __shfl_xor_sync(0xffffffffu, ps, o);
                pd += __shfl_xor_sync(0xffffffffu, pd, o);
            }
            if (lane < 4) {
                int j = nq * 32 + nt * 8 + 2 * lane + q;
                atomicAdd(&s_sm[j], ps);
                atomicAdd(&d_sm[j], pd);
            }
        }
    }

    // hT STG (f16, direct from frags)
    const __half* dummy = 0; (void)dummy;
#pragma unroll
    for (int mt = 0; mt < 4; mt++) {
        int dlo = mh * 64 + mt * 16 + (lane >> 2);
        int jg  = jloc + nq * 32 + 2 * (lane & 3);
#pragma unroll
        for (int nt = 0; nt < 4; nt++) {
            const float* cf = c[mt * 4 + nt];
            __half2 lo = __floats2half2_rn(cf[0], cf[1]);
            __half2 hi = __floats2half2_rn(cf[2], cf[3]);
            *(uint32_t*)&g_hT[((size_t)(batch * OUT_DIM + dlo)) * N_ + jg + nt * 8]
                = *(uint32_t*)&lo;
            *(uint32_t*)&g_hT[((size_t)(batch * OUT_DIM + dlo + 8)) * N_ + jg + nt * 8]
                = *(uint32_t*)&hi;
        }
    }

    __syncthreads();
    if (tid < 128) {
        float s = s_sm[tid], d = d_sm[tid];
        g_S[j0g + tid] = make_float2(expf(s * 0.5f), expf(s * 0.1f));
        g_E[j0g + tid] = make_float2(expf(d * 0.5f), expf(d * 0.1f));
    }
}

// ---------------------------------------------------------------------------
// kAB: fused masked-softmax weights + mma.sync f16 aggregation.
// 128-row CTAs (grid 128). h: 3-stage cp.async. A: register prefetch with
// full-tile gap. alpha: triple-buffered. One __syncthreads per tile.
// Warp split ms=2 (rows) x ns=4 (d).
// ---------------------------------------------------------------------------
#define HT_B     (OUT_DIM * PADH * 2)       // 18432
#define ALPHA_B  (RCTA * PADH * 2)          // 18432
#define AL_OFF   (3 * HT_B)                 // 55296
#define AB_DSM   (AL_OFF + 3 * ALPHA_B)     // 110592

__global__ void __launch_bounds__(256, 1) kAB(const float* __restrict__ A,
                                              float* __restrict__ out) {
    extern __shared__ __align__(16) char dsm[];
    __shared__ float s_z[RCTA];

    const int tid  = threadIdx.x;
    const int wid  = tid >> 5, lane = tid & 31;
    const int batch = blockIdx.x >> 5;
    const int row0  = (blockIdx.x & 31) << 7;
    const size_t rbase = (size_t)batch * N_;

    const uint32_t smb = sm_u32(dsm);
    const __half* hTb = g_hT + (size_t)batch * OUT_DIM * N_;

    const int h_dim = tid >> 3, h_ch = tid & 7;

    // weight-pass rows: wid*16..+15; lane covers cols 2l, 2l+1
    float S1[16], S2[16], z[16];
#pragma unroll
    for (int r = 0; r < 16; r++) {
        float2 sv = g_S[rbase + row0 + wid * 16 + r];
        S1[r] = sv.x; S2[r] = sv.y; z[r] = 0.f;
    }
    const float* Abase = A + (rbase + row0 + wid * 16) * (size_t)N_ + 2 * lane;

    // MMA split: mh = wid&1 (64 rows), nq = wid>>1 (32 d)
    const int mh = wid & 1, nq = wid >> 1;
    const uint32_t aoff_l = (uint32_t)((mh * 64 + (lane & 15)) * (PADH * 2)
                                       + ((lane >> 4) << 4));
    const uint32_t boff_l = (uint32_t)((nq * 32 + ((lane >> 4) << 3) + (lane & 7)) * (PADH * 2)
                                       + (((lane >> 3) & 1) << 4));

    float c[16][4];
#pragma unroll
    for (int q = 0; q < 16; q++)
        c[q][0] = c[q][1] = c[q][2] = c[q][3] = 0.f;

    float2 Ar[16];
    float4 Ev;

#define ISSUE_H(T, S)                                                         \
    do {                                                                      \
        const int jt_ = (T) * TJ;                                             \
        uint32_t hd_ = smb + (S) * HT_B;                                      \
        _Pragma("unroll")                                                     \
        for (int i = 0; i < 4; i++) {                                         \
            int dd = h_dim + i * 32;                                          \
            cp16(hd_ + dd * (PADH * 2) + h_ch * 16,                           \
                 hTb + (size_t)dd * N_ + jt_ + h_ch * 8);                     \
        }                                                                     \
        cp_commit();                                                          \
    } while (0)

#define LOAD_A(T)                                                             \
    do {                                                                      \
        Ev = ((const float4*)(g_E + rbase + (T) * TJ))[lane];                 \
        _Pragma("unroll")                                                     \
        for (int r = 0; r < 16; r++)                                          \
            Ar[r] = *(const float2*)(Abase + (size_t)r * N_ + (T) * TJ);      \
    } while (0)

#define WEIGHT(T)                                                             \
    do {                                                                      \
        __half* sal = (__half*)(dsm + AL_OFF + ((T) % 3) * ALPHA_B);          \
        _Pragma("unroll")                                                     \
        for (int r = 0; r < 16; r++) {                                        \
            float w0 = fmaxf(S1[r] * Ev.x, S2[r] * Ev.y);                     \
            float w1 = fmaxf(S1[r] * Ev.z, S2[r] * Ev.w);                     \
            w0 = Ar[r].x >= 1e-9f ? w0 : 0.f;                                 \
            w1 = Ar[r].y >= 1e-9f ? w1 : 0.f;                                 \
            z[r] += w0 + w1;                                                  \
            *(__half2*)&sal[(wid * 16 + r) * PADH + 2 * lane] =               \
                __floats2half2_rn(w0, w1);                                    \
        }                                                                     \
    } while (0)

    ISSUE_H(0, 0);
    ISSUE_H(1, 1);
    LOAD_A(0);
    WEIGHT(0);
    LOAD_A(1);

    for (int t = 0; t < NT; t++) {
        if (t + 2 < NT) cp_wait<1>();
        else            cp_wait<0>();
        __syncthreads();

        if (t + 2 < NT) ISSUE_H(t + 2, (t + 2) % 3);
        if (t + 1 < NT) {
            WEIGHT(t + 1);
            if (t + 2 < NT) LOAD_A(t + 2);
        }

        const uint32_t ab = smb + AL_OFF + (t % 3) * ALPHA_B + aoff_l;
        const uint32_t hb = smb + (t % 3) * HT_B + boff_l;
#pragma unroll
        for (int ks = 0; ks < 4; ks++) {
            uint32_t b0, b1, b2, b3, b4, b5, b6, b7;
            ldsm_x4(b0, b1, b2, b3, hb + ks * 32);
            ldsm_x4(b4, b5, b6, b7, hb + 16 * (PADH * 2) + ks * 32);
#pragma unroll
            for (int mt = 0; mt < 4; mt++) {
                uint32_t a0, a1, a2, a3;
                ldsm_x4(a0, a1, a2, a3, ab + mt * 16 * (PADH * 2) + ks * 32);
                mma16816(c[mt * 4 + 0], a0, a1, a2, a3, b0, b1);
                mma16816(c[mt * 4 + 1], a0, a1, a2, a3, b2, b3);
                mma16816(c[mt * 4 + 2], a0, a1, a2, a3, b4, b5);
                mma16816(c[mt * 4 + 3], a0, a1, a2, a3, b6, b7);
            }
        }
    }

    // z row sums
#pragma unroll
    for (int r = 0; r < 16; r++) {
        float zz = z[r];
#pragma unroll
        for (int o = 16; o; o >>= 1) zz += __shfl_xor_sync(0xffffffffu, zz, o);
        if (lane == 0) s_z[wid * 16 + r] = zz;
    }
    __syncthreads();

    // epilogue
#pragma unroll
    for (int mt = 0; mt < 4; mt++) {
        const int rlo = mh * 64 + mt * 16 + (lane >> 2);
        const float zlo = s_z[rlo], zhi = s_z[rlo + 8];
        const float invlo = zlo > 0.f ? 1.f / zlo : 0.f;
        const float invhi = zhi > 0.f ? 1.f / zhi : 0.f;
        float* olo = out + (rbase + row0 + rlo) * OUT_DIM + nq * 32 + 2 * (lane & 3);
        float* ohi = olo + 8 * OUT_DIM;
#pragma unroll
        for (int nt = 0; nt < 4; nt++) {
            const float* cf = c[mt * 4 + nt];
            *(float2*)(olo + nt * 8) = make_float2(cf[0] * invlo, cf[1] * invlo);
            *(float2*)(ohi + nt * 8) = make_float2(cf[2] * invhi, cf[3] * invhi);
        }
    }
}

// ---------------------------------------------------------------------------
extern "C" void kernel_launch(void* const* d_in, const int* in_sizes, int n_in,
                              void* d_out, int out_size) {
    const float* x     = (const float*)d_in[0];   // [4,4096,256]
    const float* A     = (const float*)d_in[1];   // [4,4096,4096]
    const float* W     = (const float*)d_in[2];   // [256,128]
    const float* a_src = (const float*)d_in[3];   // [128]
    const float* a_dst = (const float*)d_in[4];   // [128]
    float* out = (float*)d_out;                   // [4,4096,128]

    cudaFuncSetAttribute(k1_gemm, cudaFuncAttributeMaxDynamicSharedMemorySize,
                         K1_DSM);
    cudaFuncSetAttribute(kAB, cudaFuncAttributeMaxDynamicSharedMemorySize,
                         AB_DSM);

    kW     <<<8, 256>>>(W);
    k1_gemm<<<NROWS / 128, 256, K1_DSM>>>(x, a_src, a_dst);
    kAB    <<<NROWS / RCTA, 256, AB_DSM>>>(A, out);
    (void)in_sizes; (void)n_in; (void)out_size;
}